// round 7
// baseline (speedup 1.0000x reference)
#include <cuda_runtime.h>
#include <math.h>
#include <stdint.h>

#define DIM 128
#define NMAX 100000
#define MAXDEG 64

// Scratch buffers (static; no allocation allowed).
// INVARIANT: g_cursor is all-zero on entry to kernel_launch. It starts zeroed
// (module load) and agg_kernel resets every entry it reads, so the invariant
// holds across the correctness run and every graph replay.
__device__ float g_agg[NMAX * DIM];          // aggregated messages [N,128]
__device__ float g_gate[500 * DIM];          // sigmoid(rel)
__device__ int   g_cursor[NMAX];             // per-dst bucket cursor
__device__ int2  g_slots[NMAX * MAXDEG];     // (src, type) per incident edge

__device__ __forceinline__ uint32_t smem_u32(const void* p) {
    uint32_t a;
    asm("{ .reg .u64 t; cvta.to.shared.u64 t, %1; cvt.u32.u64 %0, t; }"
        : "=r"(a) : "l"(p));
    return a;
}

__device__ __forceinline__ uint32_t f2tf32(float x) {
    uint32_t t;
    asm("cvt.rna.tf32.f32 %0, %1;" : "=r"(t) : "f"(x));
    return t;
}

#define CP_ASYNC(dst, src, sz) \
    asm volatile("cp.async.ca.shared.global [%0], [%1], 16, %2;" \
                 :: "r"(dst), "l"(src), "r"(sz) : "memory")
#define CP_COMMIT() asm volatile("cp.async.commit_group;" ::: "memory")
#define CP_WAIT(n)  asm volatile("cp.async.wait_group %0;" :: "n"(n) : "memory")

__device__ __forceinline__ void mma_tf32(float* c, const uint32_t* a,
                                         const uint32_t* b) {
    asm volatile(
        "mma.sync.aligned.m16n8k8.row.col.f32.tf32.tf32.f32 "
        "{%0,%1,%2,%3}, {%4,%5,%6,%7}, {%8,%9}, {%0,%1,%2,%3};"
        : "+f"(c[0]), "+f"(c[1]), "+f"(c[2]), "+f"(c[3])
        : "r"(a[0]), "r"(a[1]), "r"(a[2]), "r"(a[3]), "r"(b[0]), "r"(b[1]));
}

// ============================================================================
// Kernel 1: prep_fill — blocks [0,250): gate=sigmoid(rel) and
// out_rel = rel @ W_rel^T + b_rel (2 rows/block). Blocks [250, ...): bucket
// each edge under its destination (cursor known zero on entry).
// ============================================================================
__global__ void prep_fill_kernel(const float* __restrict__ rel,
                                 const float* __restrict__ W_rel,
                                 const float* __restrict__ b_rel,
                                 float* __restrict__ out_rel,
                                 int R,
                                 const int* __restrict__ eidx,
                                 const int* __restrict__ etype,
                                 int E) {
    int bid = blockIdx.x;
    int tid = threadIdx.x;
    if (bid < 250) {
        __shared__ float srow[2][DIM];
        int half = tid >> 7;
        int t = tid & 127;
        int r = 2 * bid + half;
        if (r < R) {
            float x = rel[r * DIM + t];
            srow[half][t] = x;
            g_gate[r * DIM + t] = 1.f / (1.f + expf(-x));
        }
        __syncthreads();
        if (r < R) {
            float acc = b_rel[t];
            const float4* w4 = (const float4*)&W_rel[t * DIM];
#pragma unroll
            for (int k4 = 0; k4 < DIM / 4; k4++) {
                float4 w = w4[k4];
                float4 xx = *(const float4*)&srow[half][k4 * 4];
                acc += w.x * xx.x + w.y * xx.y + w.z * xx.z + w.w * xx.w;
            }
            out_rel[r * DIM + t] = acc;
        }
    } else {
        int e = (bid - 250) * 256 + tid;
        if (e < E) {
            int dst = eidx[E + e];
            int pos = atomicAdd(&g_cursor[dst], 1);
            if (pos < MAXDEG)
                g_slots[dst * MAXDEG + pos] = make_int2(eidx[e], etype[e]);
        }
    }
}

// ============================================================================
// Kernel 2: aggregate — warp per dst: sum ent[src]*gate[type] over its bucket,
// one non-atomic 512B row store. int4 slot loads (2 slots each), unroll 4,
// two accumulators -> 8 gathers in flight. Resets cursor for the next replay.
// ============================================================================
__global__ void __launch_bounds__(256)
agg_kernel(const float* __restrict__ ent, int N) {
    int warp = (blockIdx.x * blockDim.x + threadIdx.x) >> 5;
    int lane = threadIdx.x & 31;
    if (warp >= N) return;

    int deg = g_cursor[warp];
    if (lane == 0) g_cursor[warp] = 0;     // restore invariant
    if (deg > MAXDEG) deg = MAXDEG;

    const int4* sl4 = (const int4*)&g_slots[(size_t)warp * MAXDEG];
    const float4* ent4 = (const float4*)ent;
    const float4* gate4 = (const float4*)g_gate;

    float4 a0 = make_float4(0.f, 0.f, 0.f, 0.f);
    float4 a1 = make_float4(0.f, 0.f, 0.f, 0.f);

    int e = 0;
    for (; e + 4 <= deg; e += 4) {
        int4 p0 = sl4[e >> 1];
        int4 p1 = sl4[(e >> 1) + 1];
        float4 e0 = ent4[p0.x * 32 + lane];
        float4 g0 = gate4[p0.y * 32 + lane];
        float4 e1 = ent4[p0.z * 32 + lane];
        float4 g1 = gate4[p0.w * 32 + lane];
        float4 e2 = ent4[p1.x * 32 + lane];
        float4 g2 = gate4[p1.y * 32 + lane];
        float4 e3 = ent4[p1.z * 32 + lane];
        float4 g3 = gate4[p1.w * 32 + lane];
        a0.x += e0.x * g0.x + e1.x * g1.x;
        a0.y += e0.y * g0.y + e1.y * g1.y;
        a0.z += e0.z * g0.z + e1.z * g1.z;
        a0.w += e0.w * g0.w + e1.w * g1.w;
        a1.x += e2.x * g2.x + e3.x * g3.x;
        a1.y += e2.y * g2.y + e3.y * g3.y;
        a1.z += e2.z * g2.z + e3.z * g3.z;
        a1.w += e2.w * g2.w + e3.w * g3.w;
    }
    const int2* sl = (const int2*)sl4;
    for (; e < deg; e++) {
        int2 s = sl[e];
        float4 ev = ent4[s.x * 32 + lane];
        float4 gv = gate4[s.y * 32 + lane];
        a0.x += ev.x * gv.x;
        a0.y += ev.y * gv.y;
        a0.z += ev.z * gv.z;
        a0.w += ev.w * gv.w;
    }
    a0.x += a1.x; a0.y += a1.y; a0.z += a1.z; a0.w += a1.w;
    ((float4*)g_agg)[(size_t)warp * 32 + lane] = a0;
}

// ============================================================================
// Kernel 3: tf32 mma.sync GEMM (unchanged from R4/R6; 55.6us measured)
//   out = relu( X @ Wc^T + bias ),  X = [ent | agg] (K=256), Wc = [W_self|W_nei]
// ============================================================================
#define PITCH 36
#define TILE_BYTES (128 * PITCH * 4)
#define SM_AS(b)  ((b) * TILE_BYTES)
#define SM_BS(b)  (2 * TILE_BYTES + (b) * TILE_BYTES)
#define SM_BIAS   (4 * TILE_BYTES)
#define GEMM_SMEM (4 * TILE_BYTES + 512)

__global__ void __launch_bounds__(256, 2)
gemm_mma_kernel(const float* __restrict__ ent,
                const float* __restrict__ W_self,
                const float* __restrict__ b_self,
                const float* __restrict__ W_nei,
                const float* __restrict__ b_nei,
                float* __restrict__ out,
                int N) {
    extern __shared__ char smem[];
    uint32_t sb = smem_u32(smem);
    float* bias = (float*)(smem + SM_BIAS);

    int tid = threadIdx.x;
    int wid = tid >> 5;
    int lid = tid & 31;
    int wm = wid >> 2;
    int wn = wid & 3;
    int gid = lid >> 2;
    int tig = lid & 3;

    int row0 = blockIdx.x * 128;

    if (tid < 128) bias[tid] = b_self[tid] + b_nei[tid];

    auto load_chunk = [&](int kc, int buf) {
        const float* asrc = (kc < 4) ? ent : (const float*)g_agg;
        int akoff = (kc & 3) * 32;
        const float* bsrc = (kc < 4) ? W_self : W_nei;
#pragma unroll
        for (int j = 0; j < 4; j++) {
            int idx = j * 256 + tid;
            int r = idx >> 3;
            int f4 = idx & 7;
            int arow = row0 + r;
            uint32_t ad = sb + SM_AS(buf) + (uint32_t)(r * PITCH + f4 * 4) * 4;
            const float* ag = asrc + (size_t)arow * DIM + akoff + f4 * 4;
            CP_ASYNC(ad, ag, (arow < N) ? 16 : 0);
            uint32_t bd = sb + SM_BS(buf) + (uint32_t)(r * PITCH + f4 * 4) * 4;
            const float* bg = bsrc + (size_t)r * DIM + akoff + f4 * 4;
            CP_ASYNC(bd, bg, 16);
        }
        CP_COMMIT();
    };

    load_chunk(0, 0);

    float acc[4][4][4];
#pragma unroll
    for (int mt = 0; mt < 4; mt++)
#pragma unroll
        for (int nt = 0; nt < 4; nt++)
#pragma unroll
            for (int j = 0; j < 4; j++) acc[mt][nt][j] = 0.f;

    for (int kc = 0; kc < 8; kc++) {
        int buf = kc & 1;
        if (kc < 7) load_chunk(kc + 1, buf ^ 1);
        if (kc < 7) { CP_WAIT(1); } else { CP_WAIT(0); }
        __syncthreads();

        const float* As = (const float*)(smem + SM_AS(buf));
        const float* Bs = (const float*)(smem + SM_BS(buf));

#pragma unroll
        for (int s = 0; s < 4; s++) {
            uint32_t a[4][4], b[4][2];
#pragma unroll
            for (int mt = 0; mt < 4; mt++) {
                int r = wm * 64 + mt * 16 + gid;
                int c = s * 8 + tig;
                a[mt][0] = f2tf32(As[r * PITCH + c]);
                a[mt][1] = f2tf32(As[(r + 8) * PITCH + c]);
                a[mt][2] = f2tf32(As[r * PITCH + c + 4]);
                a[mt][3] = f2tf32(As[(r + 8) * PITCH + c + 4]);
            }
#pragma unroll
            for (int nt = 0; nt < 4; nt++) {
                int n = wn * 32 + nt * 8 + gid;
                int k = s * 8 + tig;
                b[nt][0] = f2tf32(Bs[n * PITCH + k]);
                b[nt][1] = f2tf32(Bs[n * PITCH + k + 4]);
            }
#pragma unroll
            for (int mt = 0; mt < 4; mt++)
#pragma unroll
                for (int nt = 0; nt < 4; nt++)
                    mma_tf32(acc[mt][nt], a[mt], b[nt]);
        }
        __syncthreads();
    }

#pragma unroll
    for (int nt = 0; nt < 4; nt++) {
        int col = wn * 32 + nt * 8 + 2 * tig;
        float b0 = bias[col], b1 = bias[col + 1];
#pragma unroll
        for (int mt = 0; mt < 4; mt++) {
            int r1 = row0 + wm * 64 + mt * 16 + gid;
            int r2 = r1 + 8;
            float* d = acc[mt][nt];
            if (r1 < N) {
                float2 v = make_float2(fmaxf(d[0] + b0, 0.f),
                                       fmaxf(d[1] + b1, 0.f));
                *(float2*)&out[(size_t)r1 * DIM + col] = v;
            }
            if (r2 < N) {
                float2 v = make_float2(fmaxf(d[2] + b0, 0.f),
                                       fmaxf(d[3] + b1, 0.f));
                *(float2*)&out[(size_t)r2 * DIM + col] = v;
            }
        }
    }
}

// ============================================================================
// Launch. Inputs: ent, rel, edge_index(int32 [2,E]), edge_type(int32 [E]),
// W_self, b_self, W_nei, b_nei, W_rel, b_rel.
// Output: out_ent [N,128] then out_rel [R,128].
// ============================================================================
extern "C" void kernel_launch(void* const* d_in, const int* in_sizes, int n_in,
                              void* d_out, int out_size) {
    const float* ent    = (const float*)d_in[0];
    const float* rel    = (const float*)d_in[1];
    const int* eidx     = (const int*)d_in[2];
    const int* etype    = (const int*)d_in[3];
    const float* W_self = (const float*)d_in[4];
    const float* b_self = (const float*)d_in[5];
    const float* W_nei  = (const float*)d_in[6];
    const float* b_nei  = (const float*)d_in[7];
    const float* W_rel  = (const float*)d_in[8];
    const float* b_rel  = (const float*)d_in[9];

    int N = in_sizes[0] / DIM;   // 100000
    int R = in_sizes[1] / DIM;   // 500
    int E = in_sizes[3];         // 600000

    float* out_ent = (float*)d_out;
    float* out_rel = (float*)d_out + (size_t)N * DIM;

    static int smem_set = 0;
    if (!smem_set) {
        cudaFuncSetAttribute(gemm_mma_kernel,
                             cudaFuncAttributeMaxDynamicSharedMemorySize,
                             GEMM_SMEM);
        smem_set = 1;
    }

    int fill_blocks = (E + 255) / 256;
    prep_fill_kernel<<<250 + fill_blocks, 256>>>(
        rel, W_rel, b_rel, out_rel, R, eidx, etype, E);

    agg_kernel<<<(N * 32 + 255) / 256, 256>>>(ent, N);

    int gemm_blocks = (N + 127) / 128;
    gemm_mma_kernel<<<gemm_blocks, 256, GEMM_SMEM>>>(
        ent, W_self, b_self, W_nei, b_nei, out_ent, N);
}

// round 8
// speedup vs baseline: 1.6460x; 1.6460x over previous
#include <cuda_runtime.h>
#include <math.h>
#include <stdint.h>

#define DIM 128
#define NMAX 100000
#define MAXDEG 64

// Scratch buffers (static; no allocation allowed).
__device__ float g_agg[NMAX * DIM];          // aggregated messages [N,128]
__device__ float g_gate[500 * DIM];          // sigmoid(rel)
__device__ int   g_cursor[NMAX];             // per-dst bucket cursor
__device__ int2  g_slots[NMAX * MAXDEG];     // (src, type) per incident edge

__device__ __forceinline__ uint32_t smem_u32(const void* p) {
    uint32_t a;
    asm("{ .reg .u64 t; cvta.to.shared.u64 t, %1; cvt.u32.u64 %0, t; }"
        : "=r"(a) : "l"(p));
    return a;
}

__device__ __forceinline__ uint32_t f2tf32(float x) {
    uint32_t t;
    asm("cvt.rna.tf32.f32 %0, %1;" : "=r"(t) : "f"(x));
    return t;
}

#define CP_ASYNC(dst, src, sz) \
    asm volatile("cp.async.ca.shared.global [%0], [%1], 16, %2;" \
                 :: "r"(dst), "l"(src), "r"(sz) : "memory")
#define CP_COMMIT() asm volatile("cp.async.commit_group;" ::: "memory")
#define CP_WAIT(n)  asm volatile("cp.async.wait_group %0;" :: "n"(n) : "memory")

__device__ __forceinline__ void mma_tf32(float* c, const uint32_t* a,
                                         const uint32_t* b) {
    asm volatile(
        "mma.sync.aligned.m16n8k8.row.col.f32.tf32.tf32.f32 "
        "{%0,%1,%2,%3}, {%4,%5,%6,%7}, {%8,%9}, {%0,%1,%2,%3};"
        : "+f"(c[0]), "+f"(c[1]), "+f"(c[2]), "+f"(c[3])
        : "r"(a[0]), "r"(a[1]), "r"(a[2]), "r"(a[3]), "r"(b[0]), "r"(b[1]));
}

// ============================================================================
// Kernel 1: prep — blocks [0,R): gate = sigmoid(rel) and
//   out_rel = rel @ W_rel^T + b_rel, one row per block, 2 threads per output
//   (each a 64-length dot with MLP=16, combined by shfl).
// Blocks [R, R+ZC): zero the cursor.
// ============================================================================
#define ZC 98
__global__ void prep_kernel(const float* __restrict__ rel,
                            const float* __restrict__ W_rel,
                            const float* __restrict__ b_rel,
                            float* __restrict__ out_rel,
                            int R, int N) {
    int bid = blockIdx.x;
    int tid = threadIdx.x;
    if (bid < R) {
        __shared__ float srow[DIM];
        int r = bid;
        if (tid < DIM) {
            float x = rel[r * DIM + tid];
            srow[tid] = x;
            g_gate[r * DIM + tid] = 1.f / (1.f + __expf(-x));
        }
        __syncthreads();
        int o    = tid >> 1;         // output 0..127
        int half = tid & 1;          // k half: [0,64) or [64,128)
        const float4* w4 = (const float4*)&W_rel[o * DIM + half * 64];
        const float4* x4 = (const float4*)&srow[half * 64];
        float acc = 0.f;
#pragma unroll
        for (int i = 0; i < 16; i++) {
            float4 w = w4[i];
            float4 xx = x4[i];
            acc += w.x * xx.x + w.y * xx.y + w.z * xx.z + w.w * xx.w;
        }
        acc += __shfl_xor_sync(0xffffffffu, acc, 1);
        if (half == 0) out_rel[r * DIM + o] = acc + b_rel[o];
    } else {
        int n4 = (N + 3) >> 2;
        for (int i = (bid - R) * 256 + tid; i < n4; i += ZC * 256)
            ((int4*)g_cursor)[i] = make_int4(0, 0, 0, 0);
    }
}

// ============================================================================
// Kernel 2: fill — bucket each edge under its destination. (R6-exact)
// ============================================================================
__global__ void fill_kernel(const int* __restrict__ eidx,
                            const int* __restrict__ etype,
                            int E) {
    int e = blockIdx.x * blockDim.x + threadIdx.x;
    if (e >= E) return;
    int dst = eidx[E + e];
    int pos = atomicAdd(&g_cursor[dst], 1);
    if (pos < MAXDEG)
        g_slots[dst * MAXDEG + pos] = make_int2(eidx[e], etype[e]);
}

// ============================================================================
// Kernel 3: aggregate — warp per dst (R6-exact body + deg clamp).
// ============================================================================
__global__ void __launch_bounds__(256)
agg_kernel(const float* __restrict__ ent, int N) {
    int warp = (blockIdx.x * blockDim.x + threadIdx.x) >> 5;
    int lane = threadIdx.x & 31;
    if (warp >= N) return;

    int deg = g_cursor[warp];
    if (deg > MAXDEG) deg = MAXDEG;
    const int2* sl = &g_slots[warp * MAXDEG];

    float4 acc = make_float4(0.f, 0.f, 0.f, 0.f);
    int e = 0;
    for (; e + 2 <= deg; e += 2) {
        int2 s0 = sl[e];
        int2 s1 = sl[e + 1];
        float4 e0 = ((const float4*)ent)[s0.x * 32 + lane];
        float4 g0 = ((const float4*)g_gate)[s0.y * 32 + lane];
        float4 e1 = ((const float4*)ent)[s1.x * 32 + lane];
        float4 g1 = ((const float4*)g_gate)[s1.y * 32 + lane];
        acc.x += e0.x * g0.x + e1.x * g1.x;
        acc.y += e0.y * g0.y + e1.y * g1.y;
        acc.z += e0.z * g0.z + e1.z * g1.z;
        acc.w += e0.w * g0.w + e1.w * g1.w;
    }
    if (e < deg) {
        int2 s0 = sl[e];
        float4 e0 = ((const float4*)ent)[s0.x * 32 + lane];
        float4 g0 = ((const float4*)g_gate)[s0.y * 32 + lane];
        acc.x += e0.x * g0.x;
        acc.y += e0.y * g0.y;
        acc.z += e0.z * g0.z;
        acc.w += e0.w * g0.w;
    }
    ((float4*)g_agg)[warp * 32 + lane] = acc;
}

// ============================================================================
// Kernel 4: tf32 mma.sync GEMM (unchanged; 55.6us measured)
//   out = relu( X @ Wc^T + bias ),  X = [ent | agg] (K=256), Wc = [W_self|W_nei]
// ============================================================================
#define PITCH 36
#define TILE_BYTES (128 * PITCH * 4)
#define SM_AS(b)  ((b) * TILE_BYTES)
#define SM_BS(b)  (2 * TILE_BYTES + (b) * TILE_BYTES)
#define SM_BIAS   (4 * TILE_BYTES)
#define GEMM_SMEM (4 * TILE_BYTES + 512)

__global__ void __launch_bounds__(256, 2)
gemm_mma_kernel(const float* __restrict__ ent,
                const float* __restrict__ W_self,
                const float* __restrict__ b_self,
                const float* __restrict__ W_nei,
                const float* __restrict__ b_nei,
                float* __restrict__ out,
                int N) {
    extern __shared__ char smem[];
    uint32_t sb = smem_u32(smem);
    float* bias = (float*)(smem + SM_BIAS);

    int tid = threadIdx.x;
    int wid = tid >> 5;
    int lid = tid & 31;
    int wm = wid >> 2;
    int wn = wid & 3;
    int gid = lid >> 2;
    int tig = lid & 3;

    int row0 = blockIdx.x * 128;

    if (tid < 128) bias[tid] = b_self[tid] + b_nei[tid];

    auto load_chunk = [&](int kc, int buf) {
        const float* asrc = (kc < 4) ? ent : (const float*)g_agg;
        int akoff = (kc & 3) * 32;
        const float* bsrc = (kc < 4) ? W_self : W_nei;
#pragma unroll
        for (int j = 0; j < 4; j++) {
            int idx = j * 256 + tid;
            int r = idx >> 3;
            int f4 = idx & 7;
            int arow = row0 + r;
            uint32_t ad = sb + SM_AS(buf) + (uint32_t)(r * PITCH + f4 * 4) * 4;
            const float* ag = asrc + (size_t)arow * DIM + akoff + f4 * 4;
            CP_ASYNC(ad, ag, (arow < N) ? 16 : 0);
            uint32_t bd = sb + SM_BS(buf) + (uint32_t)(r * PITCH + f4 * 4) * 4;
            const float* bg = bsrc + (size_t)r * DIM + akoff + f4 * 4;
            CP_ASYNC(bd, bg, 16);
        }
        CP_COMMIT();
    };

    load_chunk(0, 0);

    float acc[4][4][4];
#pragma unroll
    for (int mt = 0; mt < 4; mt++)
#pragma unroll
        for (int nt = 0; nt < 4; nt++)
#pragma unroll
            for (int j = 0; j < 4; j++) acc[mt][nt][j] = 0.f;

    for (int kc = 0; kc < 8; kc++) {
        int buf = kc & 1;
        if (kc < 7) load_chunk(kc + 1, buf ^ 1);
        if (kc < 7) { CP_WAIT(1); } else { CP_WAIT(0); }
        __syncthreads();

        const float* As = (const float*)(smem + SM_AS(buf));
        const float* Bs = (const float*)(smem + SM_BS(buf));

#pragma unroll
        for (int s = 0; s < 4; s++) {
            uint32_t a[4][4], b[4][2];
#pragma unroll
            for (int mt = 0; mt < 4; mt++) {
                int r = wm * 64 + mt * 16 + gid;
                int c = s * 8 + tig;
                a[mt][0] = f2tf32(As[r * PITCH + c]);
                a[mt][1] = f2tf32(As[(r + 8) * PITCH + c]);
                a[mt][2] = f2tf32(As[r * PITCH + c + 4]);
                a[mt][3] = f2tf32(As[(r + 8) * PITCH + c + 4]);
            }
#pragma unroll
            for (int nt = 0; nt < 4; nt++) {
                int n = wn * 32 + nt * 8 + gid;
                int k = s * 8 + tig;
                b[nt][0] = f2tf32(Bs[n * PITCH + k]);
                b[nt][1] = f2tf32(Bs[n * PITCH + k + 4]);
            }
#pragma unroll
            for (int mt = 0; mt < 4; mt++)
#pragma unroll
                for (int nt = 0; nt < 4; nt++)
                    mma_tf32(acc[mt][nt], a[mt], b[nt]);
        }
        __syncthreads();
    }

#pragma unroll
    for (int nt = 0; nt < 4; nt++) {
        int col = wn * 32 + nt * 8 + 2 * tig;
        float b0 = bias[col], b1 = bias[col + 1];
#pragma unroll
        for (int mt = 0; mt < 4; mt++) {
            int r1 = row0 + wm * 64 + mt * 16 + gid;
            int r2 = r1 + 8;
            float* d = acc[mt][nt];
            if (r1 < N) {
                float2 v = make_float2(fmaxf(d[0] + b0, 0.f),
                                       fmaxf(d[1] + b1, 0.f));
                *(float2*)&out[(size_t)r1 * DIM + col] = v;
            }
            if (r2 < N) {
                float2 v = make_float2(fmaxf(d[2] + b0, 0.f),
                                       fmaxf(d[3] + b1, 0.f));
                *(float2*)&out[(size_t)r2 * DIM + col] = v;
            }
        }
    }
}

// ============================================================================
// Launch. Inputs: ent, rel, edge_index(int32 [2,E]), edge_type(int32 [E]),
// W_self, b_self, W_nei, b_nei, W_rel, b_rel.
// Output: out_ent [N,128] then out_rel [R,128].
// ============================================================================
extern "C" void kernel_launch(void* const* d_in, const int* in_sizes, int n_in,
                              void* d_out, int out_size) {
    const float* ent    = (const float*)d_in[0];
    const float* rel    = (const float*)d_in[1];
    const int* eidx     = (const int*)d_in[2];
    const int* etype    = (const int*)d_in[3];
    const float* W_self = (const float*)d_in[4];
    const float* b_self = (const float*)d_in[5];
    const float* W_nei  = (const float*)d_in[6];
    const float* b_nei  = (const float*)d_in[7];
    const float* W_rel  = (const float*)d_in[8];
    const float* b_rel  = (const float*)d_in[9];

    int N = in_sizes[0] / DIM;   // 100000
    int R = in_sizes[1] / DIM;   // 500
    int E = in_sizes[3];         // 600000

    float* out_ent = (float*)d_out;
    float* out_rel = (float*)d_out + (size_t)N * DIM;

    static int smem_set = 0;
    if (!smem_set) {
        cudaFuncSetAttribute(gemm_mma_kernel,
                             cudaFuncAttributeMaxDynamicSharedMemorySize,
                             GEMM_SMEM);
        smem_set = 1;
    }

    prep_kernel<<<R + ZC, 256>>>(rel, W_rel, b_rel, out_rel, R, N);

    fill_kernel<<<(E + 255) / 256, 256>>>(eidx, etype, E);

    agg_kernel<<<(N * 32 + 255) / 256, 256>>>(ent, N);

    int gemm_blocks = (N + 127) / 128;
    gemm_mma_kernel<<<gemm_blocks, 256, GEMM_SMEM>>>(
        ent, W_self, b_self, W_nei, b_nei, out_ent, N);
}